// round 3
// baseline (speedup 1.0000x reference)
#include <cuda_runtime.h>
#include <cstdint>
#include <cstddef>

// ============================================================================
// ConvLSTM encoder == 3-layer stacked LSTM (K=3 conv over a length-1 spatial
// dim, pad 1 -> only center tap W[:,:,1] contributes).
//
// Hang-proof multi-launch pipeline: launch j computes layer0@t=j,
// layer1@t=j-1, layer2@t=j-2. All dependencies are kernel-boundary ordering.
//   h: double-buffered by launch parity.  c: updated in place.
//   Weights packed once per call into dense [l][k][o] (center tap only).
// ============================================================================

#define BBATCH 256
#define HHID   128
#define CIN    64
#define JC_N   16                      // j-chunks per layer (8 hidden each)
#define BG_N   3                       // batch groups (85/85/86)
#define CTA_PER_LAYER (JC_N*BG_N)      // 48
#define GRID_MAIN (3*CTA_PER_LAYER)    // 144
#define NTHR 256

// SMEM (floats): Ash [K<=256][97] | Wsh2 (splat pairs) [256][64] | Gsh [32][98]
#define ASH_OFF 0
#define ASTR    97
#define WSH_OFF (256*ASTR)                 // 24832
#define GSH_OFF (WSH_OFF + 256*64)         // 41216
#define GSTR    98
#define SMEM_FLOATS (GSH_OFF + 32*GSTR)    // 44352
#define SMEM_BYTES  (SMEM_FLOATS*4)        // 177408

__device__ float g_wpack[3][256][512];           // [l][k][o], 1.5 MB
__device__ float g_h[2][3][BBATCH][HHID];        // parity double buffer
__device__ float g_c[3][BBATCH][HHID];

// ---------------------------------------------------------------------------
__device__ __forceinline__ float2 ffma2(float2 a, float2 b, float2 c) {
    unsigned long long ua = *reinterpret_cast<unsigned long long*>(&a);
    unsigned long long ub = *reinterpret_cast<unsigned long long*>(&b);
    unsigned long long uc = *reinterpret_cast<unsigned long long*>(&c);
    unsigned long long ud;
    asm("fma.rn.f32x2 %0, %1, %2, %3;" : "=l"(ud) : "l"(ua), "l"(ub), "l"(uc));
    float2 d;
    *reinterpret_cast<unsigned long long*>(&d) = ud;
    return d;
}

// ---------------------------------------------------------------------------
__global__ void prep_kernel(const float* __restrict__ W1,
                            const float* __restrict__ W2,
                            const float* __restrict__ W3)
{
    for (int u = blockIdx.x * blockDim.x + threadIdx.x;
         u < 3 * 256 * 512; u += gridDim.x * blockDim.x) {
        const int l   = u / (256 * 512);
        const int rem = u - l * 256 * 512;
        const int k   = rem >> 9;          // /512
        const int o   = rem & 511;
        const int K   = (l == 0) ? (CIN + HHID) : (2 * HHID);
        if (k < K) {
            const float* W = (l == 0) ? W1 : ((l == 1) ? W2 : W3);
            g_wpack[l][k][o] = W[((size_t)o * K + k) * 3 + 1];
        }
    }
}

// ---------------------------------------------------------------------------
__global__ void __launch_bounds__(NTHR, 1)
step_kernel(const float* __restrict__ x,
            const float* __restrict__ b1, const float* __restrict__ b2,
            const float* __restrict__ b3,
            const float* __restrict__ h01, const float* __restrict__ c01,
            const float* __restrict__ h02, const float* __restrict__ c02,
            const float* __restrict__ h03, const float* __restrict__ c03,
            float* __restrict__ out, int jstep, int T, int Tx)
{
    const int l = blockIdx.x / CTA_PER_LAYER;
    const int t = jstep - l;
    if (t < 0 || t >= T) return;

    extern __shared__ float sm[];
    const int tid = threadIdx.x;
    const int r   = blockIdx.x % CTA_PER_LAYER;
    const int jc  = r % JC_N;
    const int bg  = r / JC_N;
    const int b0   = (bg * BBATCH) / BG_N;
    const int bcnt = ((bg + 1) * BBATCH) / BG_N - b0;    // 85/85/86
    const int Kin  = (l == 0) ? CIN : HHID;
    const int K    = Kin + HHID;                          // 192 or 256
    const int q    = (jstep - 1) & 1;                     // read parity

    const float* bl  = (l == 0) ? b1  : ((l == 1) ? b2  : b3);
    const float* h0l = (l == 0) ? h01 : ((l == 1) ? h02 : h03);
    const float* c0l = (l == 0) ? c01 : ((l == 1) ? c02 : c03);

    // ---- stage weights as splat pairs: Wsh2[kk][2*r..] = {w_r, w_r} -------
    for (int u = tid; u < K * 8; u += NTHR) {
        const int kk = u >> 3;
        const int s  = u & 7;
        const int g  = s >> 1;
        const int jb = (s & 1) * 4;
        const int o  = g * 128 + jc * 8 + jb;
        const float4 w = *reinterpret_cast<const float4*>(&g_wpack[l][kk][o]);
        float* W2p = sm + WSH_OFF + kk * 64 + (g * 8 + jb) * 2;
        reinterpret_cast<float4*>(W2p)[0] = make_float4(w.x, w.x, w.y, w.y);
        reinterpret_cast<float4*>(W2p)[1] = make_float4(w.z, w.z, w.w, w.w);
    }

    // ---- stage activations: Ash[k][m], stride 97 --------------------------
    const int kz4 = Kin >> 2;
    for (int u = tid; u < kz4 * bcnt; u += NTHR) {
        const int m  = u / kz4;
        const int k4 = u - m * kz4;
        float4 v;
        if (l == 0)
            v = reinterpret_cast<const float4*>(
                    x + ((size_t)(b0 + m) * Tx + t) * CIN)[k4];
        else
            v = reinterpret_cast<const float4*>(g_h[q][l - 1][b0 + m])[k4];
        float* A = sm + ASH_OFF + (k4 * 4) * ASTR + m;
        A[0] = v.x; A[ASTR] = v.y; A[2 * ASTR] = v.z; A[3 * ASTR] = v.w;
    }
    for (int u = tid; u < 32 * bcnt; u += NTHR) {          // HHID/4 = 32
        const int m  = u >> 5;
        const int k4 = u & 31;
        const float4 v = (t == 0)
            ? reinterpret_cast<const float4*>(h0l + (b0 + m) * HHID)[k4]
            : reinterpret_cast<const float4*>(g_h[q][l][b0 + m])[k4];
        float* A = sm + ASH_OFF + (Kin + k4 * 4) * ASTR + m;
        A[0] = v.x; A[ASTR] = v.y; A[2 * ASTR] = v.z; A[3 * ASTR] = v.w;
    }
    __syncthreads();

    // ---- GEMM: rows r0,r0+1 (2 of 32) x cols tx*6..+5 ---------------------
    const int tx = tid & 15, ty = tid >> 4;
    const int r0 = ty * 2;
    const int gq = r0 >> 3, jj0 = r0 & 7;
    const float bb0 = bl[gq * 128 + jc * 8 + jj0];
    const float bb1 = bl[gq * 128 + jc * 8 + jj0 + 1];
    float2 acc0[3], acc1[3];
    #pragma unroll
    for (int cp = 0; cp < 3; ++cp) {
        acc0[cp] = make_float2(bb0, bb0);
        acc1[cp] = make_float2(bb1, bb1);
    }
    const float* Wp = sm + WSH_OFF + ty * 4;
    const float* Ap = sm + ASH_OFF + tx * 6;
    #pragma unroll 4
    for (int kk = 0; kk < K; ++kk) {
        const float4 w = *reinterpret_cast<const float4*>(Wp + kk * 64);
        const float2 w0p = make_float2(w.x, w.y);   // {w_r0, w_r0}
        const float2 w1p = make_float2(w.z, w.w);   // {w_r1, w_r1}
        const float* A = Ap + kk * ASTR;
        const float2 p0 = make_float2(A[0], A[1]);
        const float2 p1 = make_float2(A[2], A[3]);
        const float2 p2 = make_float2(A[4], A[5]);
        acc0[0] = ffma2(p0, w0p, acc0[0]);
        acc1[0] = ffma2(p0, w1p, acc1[0]);
        acc0[1] = ffma2(p1, w0p, acc0[1]);
        acc1[1] = ffma2(p1, w1p, acc1[1]);
        acc0[2] = ffma2(p2, w0p, acc0[2]);
        acc1[2] = ffma2(p2, w1p, acc1[2]);
    }
    {
        float* Gp = sm + GSH_OFF + r0 * GSTR + tx * 6;
        Gp[0] = acc0[0].x; Gp[1] = acc0[0].y; Gp[2] = acc0[1].x;
        Gp[3] = acc0[1].y; Gp[4] = acc0[2].x; Gp[5] = acc0[2].y;
        Gp += GSTR;
        Gp[0] = acc1[0].x; Gp[1] = acc1[0].y; Gp[2] = acc1[1].x;
        Gp[3] = acc1[1].y; Gp[4] = acc1[2].x; Gp[5] = acc1[2].y;
    }
    __syncthreads();

    // ---- pointwise LSTM; publish h (parity jstep&1), c in place -----------
    const int p = jstep & 1;
    for (int i = tid; i < 8 * bcnt; i += NTHR) {
        const int jj = i & 7, m = i >> 3;
        const float gi = sm[GSH_OFF + jj * GSTR + m];
        const float gf = sm[GSH_OFF + (8 + jj) * GSTR + m];
        const float go = sm[GSH_OFF + (16 + jj) * GSTR + m];
        const float gg = sm[GSH_OFF + (24 + jj) * GSTR + m];
        const int b = b0 + m, jg = jc * 8 + jj;
        float c = (t == 0) ? c0l[b * HHID + jg] : g_c[l][b][jg];
        const float si = __fdividef(1.f, 1.f + __expf(-gi));
        const float sf = __fdividef(1.f, 1.f + __expf(-gf));
        const float so = __fdividef(1.f, 1.f + __expf(-go));
        c = sf * c + si * tanhf(gg);
        const float h = so * tanhf(c);
        g_c[l][b][jg] = c;
        g_h[p][l][b][jg] = h;
        if (l == 2 && t == T - 1)
            out[b * HHID + jg] = h;
    }
}

// ---------------------------------------------------------------------------
extern "C" void kernel_launch(void* const* d_in, const int* in_sizes, int n_in,
                              void* d_out, int out_size)
{
    const float* x   = (const float*)d_in[0];
    const float* W1  = (const float*)d_in[1];
    const float* b1  = (const float*)d_in[2];
    const float* W2  = (const float*)d_in[3];
    const float* b2  = (const float*)d_in[4];
    const float* W3  = (const float*)d_in[5];
    const float* b3  = (const float*)d_in[6];
    const float* h01 = (const float*)d_in[7];
    const float* c01 = (const float*)d_in[8];
    const float* h02 = (const float*)d_in[9];
    const float* c02 = (const float*)d_in[10];
    const float* h03 = (const float*)d_in[11];
    const float* c03 = (const float*)d_in[12];
    float* out = (float*)d_out;
    (void)n_in; (void)out_size;

    const int Tx = in_sizes[0] / (BBATCH * CIN);   // = 512 = seq_len
    const int T  = Tx;

    cudaFuncSetAttribute(step_kernel,
                         cudaFuncAttributeMaxDynamicSharedMemorySize,
                         SMEM_BYTES);

    prep_kernel<<<192, 256>>>(W1, W2, W3);
    for (int j = 0; j < T + 2; ++j)
        step_kernel<<<GRID_MAIN, NTHR, SMEM_BYTES>>>(
            x, b1, b2, b3, h01, c01, h02, c02, h03, c03,
            out, j, T, Tx);
}

// round 5
// speedup vs baseline: 1.0131x; 1.0131x over previous
#include <cuda_runtime.h>
#include <cstdint>
#include <cstddef>

// ============================================================================
// ConvLSTM encoder == 3-layer stacked LSTM (K=3 conv over a length-1 spatial
// dim, pad 1 -> only center tap W[:,:,1] contributes).
//
// Multi-launch skewed pipeline (proven): launch j computes layer0@t=j,
// layer1@t=j-1, layer2@t=j-2; dependencies are kernel-boundary ordering.
// This round: software-pipelined fp32x2 GEMM core + contiguous weight staging.
// ============================================================================

#define BBATCH 256
#define HHID   128
#define CIN    64
#define JC_N   16                      // hidden chunks per layer (8 hidden each)
#define BG_N   3                       // batch groups (85/85/86)
#define CTA_PER_LAYER (JC_N*BG_N)      // 48
#define GRID_MAIN (3*CTA_PER_LAYER)    // 144
#define NTHR 256

// SMEM (floats): Ash [256][98] | Wsh splat pairs [256][64] | Gsh [32][98]
#define ASTR    98
#define ASH_OFF 0
#define WSH_OFF (256*ASTR)                  // 25088
#define GSH_OFF (WSH_OFF + 256*64)          // 41472
#define GSTR    98
#define SMEM_FLOATS (GSH_OFF + 32*GSTR)     // 44608
#define SMEM_BYTES  (SMEM_FLOATS*4)         // 178432

// Weight pack: per (layer, jc-chunk): [k][64] = splat pairs of the 32 gate
// rows owned by that chunk. 3*16*256*64 floats = 3 MB (L2-resident).
__device__ float g_wsplat[3*16*256*64];
__device__ float g_h[2][3][BBATCH][HHID];        // parity double buffer
__device__ float g_c[3][BBATCH][HHID];

// ---------------------------------------------------------------------------
__device__ __forceinline__ float2 ffma2(float2 a, float2 b, float2 c) {
    unsigned long long ua = *reinterpret_cast<unsigned long long*>(&a);
    unsigned long long ub = *reinterpret_cast<unsigned long long*>(&b);
    unsigned long long uc = *reinterpret_cast<unsigned long long*>(&c);
    unsigned long long ud;
    asm("fma.rn.f32x2 %0, %1, %2, %3;" : "=l"(ud) : "l"(ua), "l"(ub), "l"(uc));
    float2 d;
    *reinterpret_cast<unsigned long long*>(&d) = ud;
    return d;
}

// ---------------------------------------------------------------------------
// Build g_wsplat: for (l, jc, k, r<32): row o = (r>>3)*128 + jc*8 + (r&7);
// value W[o][k][1] written twice at [..][k][2r] and [2r+1].
__global__ void prep_kernel(const float* __restrict__ W1,
                            const float* __restrict__ W2,
                            const float* __restrict__ W3)
{
    const int total = 3 * 16 * 256 * 32;
    for (int u = blockIdx.x * blockDim.x + threadIdx.x;
         u < total; u += gridDim.x * blockDim.x) {
        const int r  = u & 31;
        const int k  = (u >> 5) & 255;
        const int jc = (u >> 13) & 15;
        const int l  = u >> 17;
        const int K  = (l == 0) ? (CIN + HHID) : (2 * HHID);
        if (k < K) {
            const float* W = (l == 0) ? W1 : ((l == 1) ? W2 : W3);
            const int o = (r >> 3) * 128 + jc * 8 + (r & 7);
            const float v = W[((size_t)o * K + k) * 3 + 1];
            float* dst = g_wsplat + (((l * 16 + jc) * 256 + k) << 6) + 2 * r;
            dst[0] = v;
            dst[1] = v;
        }
    }
}

// ---------------------------------------------------------------------------
// Double-buffered GEMM building blocks (functions, not macros: a macro param
// named `w` would capture the `.w` member access of float4).
struct KBlk {
    float4 wv[4];
    float2 av[4][3];
};

__device__ __forceinline__ void load_blk(KBlk& B, const float4* W4,
                                         const float* Ap, int kb)
{
    const float4* Wp = W4 + kb * 64;
    const float*  A  = Ap + kb * (4 * ASTR);
    #pragma unroll
    for (int i = 0; i < 4; ++i) {
        B.wv[i] = Wp[i * 16];
        const float* a = A + i * ASTR;
        B.av[i][0] = *reinterpret_cast<const float2*>(a);
        B.av[i][1] = *reinterpret_cast<const float2*>(a + 2);
        B.av[i][2] = *reinterpret_cast<const float2*>(a + 4);
    }
}

__device__ __forceinline__ void fma_blk(const KBlk& B,
                                        float2& acc00, float2& acc01,
                                        float2& acc02, float2& acc10,
                                        float2& acc11, float2& acc12)
{
    #pragma unroll
    for (int i = 0; i < 4; ++i) {
        const float2 w01 = make_float2(B.wv[i].x, B.wv[i].y);
        const float2 w23 = make_float2(B.wv[i].z, B.wv[i].w);
        acc00 = ffma2(B.av[i][0], w01, acc00);
        acc10 = ffma2(B.av[i][0], w23, acc10);
        acc01 = ffma2(B.av[i][1], w01, acc01);
        acc11 = ffma2(B.av[i][1], w23, acc11);
        acc02 = ffma2(B.av[i][2], w01, acc02);
        acc12 = ffma2(B.av[i][2], w23, acc12);
    }
}

__global__ void __launch_bounds__(NTHR)
step_kernel(const float* __restrict__ x,
            const float* __restrict__ b1, const float* __restrict__ b2,
            const float* __restrict__ b3,
            const float* __restrict__ h01, const float* __restrict__ c01,
            const float* __restrict__ h02, const float* __restrict__ c02,
            const float* __restrict__ h03, const float* __restrict__ c03,
            float* __restrict__ out, int jstep, int T, int Tx)
{
    const int l = blockIdx.x / CTA_PER_LAYER;
    const int t = jstep - l;
    if (t < 0 || t >= T) return;

    extern __shared__ float sm[];
    const int tid = threadIdx.x;
    const int r   = blockIdx.x % CTA_PER_LAYER;
    const int jc  = r % JC_N;
    const int bg  = r / JC_N;
    const int b0   = (bg * BBATCH) / BG_N;
    const int bcnt = ((bg + 1) * BBATCH) / BG_N - b0;    // 85/85/86
    const int Kin  = (l == 0) ? CIN : HHID;
    const int K    = Kin + HHID;                          // 192 or 256
    const int q    = (jstep - 1) & 1;                     // read parity

    const float* bl  = (l == 0) ? b1  : ((l == 1) ? b2  : b3);
    const float* h0l = (l == 0) ? h01 : ((l == 1) ? h02 : h03);
    const float* c0l = (l == 0) ? c01 : ((l == 1) ? c02 : c03);

    // ---- stage weights: contiguous float4 copy of the pre-splatted chunk --
    {
        const float4* src = reinterpret_cast<const float4*>(
            g_wsplat + ((size_t)(l * 16 + jc) << 14));    // *256*64
        float4* dst = reinterpret_cast<float4*>(sm + WSH_OFF);
        const int n4 = K * 16;                            // K*64/4
        for (int u = tid; u < n4; u += NTHR)
            dst[u] = src[u];
    }

    // ---- stage activations: Ash[k][m], stride 98 --------------------------
    {
        const int kz4 = Kin >> 2;
        for (int u = tid; u < kz4 * bcnt; u += NTHR) {
            const int m  = u / kz4;
            const int k4 = u - m * kz4;
            float4 v;
            if (l == 0)
                v = reinterpret_cast<const float4*>(
                        x + ((size_t)(b0 + m) * Tx + t) * CIN)[k4];
            else
                v = reinterpret_cast<const float4*>(g_h[q][l - 1][b0 + m])[k4];
            float* A = sm + ASH_OFF + (k4 * 4) * ASTR + m;
            A[0] = v.x; A[ASTR] = v.y; A[2 * ASTR] = v.z; A[3 * ASTR] = v.w;
        }
        for (int u = tid; u < 32 * bcnt; u += NTHR) {      // HHID/4 = 32
            const int m  = u >> 5;
            const int k4 = u & 31;
            const float4 v = (t == 0)
                ? reinterpret_cast<const float4*>(h0l + (b0 + m) * HHID)[k4]
                : reinterpret_cast<const float4*>(g_h[q][l][b0 + m])[k4];
            float* A = sm + ASH_OFF + (Kin + k4 * 4) * ASTR + m;
            A[0] = v.x; A[ASTR] = v.y; A[2 * ASTR] = v.z; A[3 * ASTR] = v.w;
        }
    }
    __syncthreads();

    // ---- GEMM: thread (tx, ty): rows {2ty, 2ty+1} x cols {tx*6..tx*6+5} ---
    const int tx = tid & 15, ty = tid >> 4;
    const int r0 = 2 * ty;
    const float bb0 = bl[(r0 >> 3) * 128 + jc * 8 + (r0 & 7)];
    const float bb1 = bl[(r0 >> 3) * 128 + jc * 8 + (r0 & 7) + 1];

    float2 acc00 = make_float2(bb0, bb0), acc01 = acc00, acc02 = acc00;
    float2 acc10 = make_float2(bb1, bb1), acc11 = acc10, acc12 = acc10;

    const float4* W4 = reinterpret_cast<const float4*>(sm + WSH_OFF) + ty;
    const float*  Ap = sm + ASH_OFF + tx * 6;

    KBlk bufA, bufB;
    const int nkb = K >> 2;                // 48 or 64 (even)

    load_blk(bufA, W4, Ap, 0);
    int kb = 0;
    #pragma unroll 1
    for (; kb + 2 < nkb; kb += 2) {
        load_blk(bufB, W4, Ap, kb + 1);
        fma_blk(bufA, acc00, acc01, acc02, acc10, acc11, acc12);
        load_blk(bufA, W4, Ap, kb + 2);
        fma_blk(bufB, acc00, acc01, acc02, acc10, acc11, acc12);
    }
    load_blk(bufB, W4, Ap, kb + 1);
    fma_blk(bufA, acc00, acc01, acc02, acc10, acc11, acc12);
    fma_blk(bufB, acc00, acc01, acc02, acc10, acc11, acc12);

    {
        float* Gp0 = sm + GSH_OFF + r0 * GSTR + tx * 6;
        float* Gp1 = Gp0 + GSTR;
        *reinterpret_cast<float2*>(Gp0    ) = make_float2(acc00.x, acc00.y);
        *reinterpret_cast<float2*>(Gp0 + 2) = make_float2(acc01.x, acc01.y);
        *reinterpret_cast<float2*>(Gp0 + 4) = make_float2(acc02.x, acc02.y);
        *reinterpret_cast<float2*>(Gp1    ) = make_float2(acc10.x, acc10.y);
        *reinterpret_cast<float2*>(Gp1 + 2) = make_float2(acc11.x, acc11.y);
        *reinterpret_cast<float2*>(Gp1 + 4) = make_float2(acc12.x, acc12.y);
    }
    __syncthreads();

    // ---- pointwise LSTM; publish h (parity jstep&1), c in place -----------
    const int p = jstep & 1;
    for (int i = tid; i < 8 * bcnt; i += NTHR) {
        const int jj = i & 7, m = i >> 3;
        const float gi = sm[GSH_OFF + (     jj) * GSTR + m];
        const float gf = sm[GSH_OFF + ( 8 + jj) * GSTR + m];
        const float go = sm[GSH_OFF + (16 + jj) * GSTR + m];
        const float gg = sm[GSH_OFF + (24 + jj) * GSTR + m];
        const int b = b0 + m, jg = jc * 8 + jj;
        float c = (t == 0) ? c0l[b * HHID + jg] : g_c[l][b][jg];
        const float si = __fdividef(1.f, 1.f + __expf(-gi));
        const float sf = __fdividef(1.f, 1.f + __expf(-gf));
        const float so = __fdividef(1.f, 1.f + __expf(-go));
        c = sf * c + si * tanhf(gg);
        const float h = so * tanhf(c);
        g_c[l][b][jg] = c;
        g_h[p][l][b][jg] = h;
        if (l == 2 && t == T - 1)
            out[b * HHID + jg] = h;
    }
}

// ---------------------------------------------------------------------------
extern "C" void kernel_launch(void* const* d_in, const int* in_sizes, int n_in,
                              void* d_out, int out_size)
{
    const float* x   = (const float*)d_in[0];
    const float* W1  = (const float*)d_in[1];
    const float* b1  = (const float*)d_in[2];
    const float* W2  = (const float*)d_in[3];
    const float* b2  = (const float*)d_in[4];
    const float* W3  = (const float*)d_in[5];
    const float* b3  = (const float*)d_in[6];
    const float* h01 = (const float*)d_in[7];
    const float* c01 = (const float*)d_in[8];
    const float* h02 = (const float*)d_in[9];
    const float* c02 = (const float*)d_in[10];
    const float* h03 = (const float*)d_in[11];
    const float* c03 = (const float*)d_in[12];
    float* out = (float*)d_out;
    (void)n_in; (void)out_size;

    const int Tx = in_sizes[0] / (BBATCH * CIN);   // = 512 = seq_len
    const int T  = Tx;

    cudaFuncSetAttribute(step_kernel,
                         cudaFuncAttributeMaxDynamicSharedMemorySize,
                         SMEM_BYTES);

    prep_kernel<<<192, 256>>>(W1, W2, W3);
    for (int j = 0; j < T + 2; ++j)
        step_kernel<<<GRID_MAIN, NTHR, SMEM_BYTES>>>(
            x, b1, b2, b3, h01, c01, h02, c02, h03, c03,
            out, j, T, Tx);
}

// round 6
// speedup vs baseline: 1.0498x; 1.0362x over previous
#include <cuda_runtime.h>
#include <cstdint>
#include <cstddef>

// ============================================================================
// ConvLSTM encoder == 3-layer stacked LSTM (K=3 conv over a length-1 spatial
// dim, pad 1 -> only center tap W[:,:,1] contributes).
//
// Multi-launch skewed pipeline: launch j computes layer0@t=j, layer1@t=j-1,
// layer2@t=j-2; dependencies are kernel-boundary ordering.
// This round: split-K x2 -> 512 threads (16 warps/SM) for latency hiding;
// conflict-free activation staging.
// ============================================================================

#define BBATCH 256
#define HHID   128
#define CIN    64
#define JC_N   16                      // hidden chunks per layer (8 hidden each)
#define BG_N   3                       // batch groups (85/85/86)
#define CTA_PER_LAYER (JC_N*BG_N)      // 48
#define GRID_MAIN (3*CTA_PER_LAYER)    // 144
#define NTHR 512

// SMEM (floats): Ash [256][98] | Wsh splat pairs [256][64] | Gsh [2][32][98]
#define ASTR    98
#define ASH_OFF 0
#define WSH_OFF (256*ASTR)                  // 25088
#define GSH_OFF (WSH_OFF + 256*64)          // 41472
#define GSTR    98
#define SMEM_FLOATS (GSH_OFF + 2*32*GSTR)   // 47744
#define SMEM_BYTES  (SMEM_FLOATS*4)         // 190976 B (< 227KB opt-in)

// Weight pack: per (layer, jc-chunk): [k][64] = splat pairs of the 32 gate
// rows owned by that chunk. 3 MB, L2-resident.
__device__ float g_wsplat[3*16*256*64];
__device__ float g_h[2][3][BBATCH][HHID];        // parity double buffer
__device__ float g_c[3][BBATCH][HHID];

// ---------------------------------------------------------------------------
__device__ __forceinline__ float2 ffma2(float2 a, float2 b, float2 c) {
    unsigned long long ua = *reinterpret_cast<unsigned long long*>(&a);
    unsigned long long ub = *reinterpret_cast<unsigned long long*>(&b);
    unsigned long long uc = *reinterpret_cast<unsigned long long*>(&c);
    unsigned long long ud;
    asm("fma.rn.f32x2 %0, %1, %2, %3;" : "=l"(ud) : "l"(ua), "l"(ub), "l"(uc));
    float2 d;
    *reinterpret_cast<unsigned long long*>(&d) = ud;
    return d;
}

// ---------------------------------------------------------------------------
// Build g_wsplat: for (l, jc, k, r<32): row o = (r>>3)*128 + jc*8 + (r&7);
// value W[o][k][1] written twice at [..][k][2r] and [2r+1].
__global__ void prep_kernel(const float* __restrict__ W1,
                            const float* __restrict__ W2,
                            const float* __restrict__ W3)
{
    const int total = 3 * 16 * 256 * 32;
    for (int u = blockIdx.x * blockDim.x + threadIdx.x;
         u < total; u += gridDim.x * blockDim.x) {
        const int r  = u & 31;
        const int k  = (u >> 5) & 255;
        const int jc = (u >> 13) & 15;
        const int l  = u >> 17;
        const int K  = (l == 0) ? (CIN + HHID) : (2 * HHID);
        if (k < K) {
            const float* W = (l == 0) ? W1 : ((l == 1) ? W2 : W3);
            const int o = (r >> 3) * 128 + jc * 8 + (r & 7);
            const float v = W[((size_t)o * K + k) * 3 + 1];
            float* dst = g_wsplat + (((l * 16 + jc) * 256 + k) << 6) + 2 * r;
            dst[0] = v;
            dst[1] = v;
        }
    }
}

// ---------------------------------------------------------------------------
__global__ void __launch_bounds__(NTHR)
step_kernel(const float* __restrict__ x,
            const float* __restrict__ b1, const float* __restrict__ b2,
            const float* __restrict__ b3,
            const float* __restrict__ h01, const float* __restrict__ c01,
            const float* __restrict__ h02, const float* __restrict__ c02,
            const float* __restrict__ h03, const float* __restrict__ c03,
            float* __restrict__ out, int jstep, int T, int Tx)
{
    const int l = blockIdx.x / CTA_PER_LAYER;
    const int t = jstep - l;
    if (t < 0 || t >= T) return;

    extern __shared__ float sm[];
    const int tid = threadIdx.x;
    const int r   = blockIdx.x % CTA_PER_LAYER;
    const int jc  = r % JC_N;
    const int bg  = r / JC_N;
    const int b0   = (bg * BBATCH) / BG_N;
    const int bcnt = ((bg + 1) * BBATCH) / BG_N - b0;    // 85/85/86
    const int Kin  = (l == 0) ? CIN : HHID;
    const int K    = Kin + HHID;                          // 192 or 256
    const int q    = (jstep - 1) & 1;                     // read parity

    const float* bl  = (l == 0) ? b1  : ((l == 1) ? b2  : b3);
    const float* h0l = (l == 0) ? h01 : ((l == 1) ? h02 : h03);
    const float* c0l = (l == 0) ? c01 : ((l == 1) ? c02 : c03);

    // ---- stage weights: contiguous float4 copy of the pre-splatted chunk --
    {
        const float4* src = reinterpret_cast<const float4*>(
            g_wsplat + ((size_t)(l * 16 + jc) << 14));    // *256*64
        float4* dst = reinterpret_cast<float4*>(sm + WSH_OFF);
        const int n4 = K * 16;                            // K*64/4
        for (int u = tid; u < n4; u += NTHR)
            dst[u] = src[u];
    }

    // ---- stage activations: Ash[k][m], m-fast (conflict-free STS) ---------
    {
        const int kz4 = Kin >> 2;
        for (int u = tid; u < kz4 * bcnt; u += NTHR) {
            const int k4 = u / bcnt;
            const int m  = u - k4 * bcnt;
            float4 v;
            if (l == 0)
                v = reinterpret_cast<const float4*>(
                        x + ((size_t)(b0 + m) * Tx + t) * CIN)[k4];
            else
                v = reinterpret_cast<const float4*>(g_h[q][l - 1][b0 + m])[k4];
            float* A = sm + ASH_OFF + (k4 * 4) * ASTR + m;
            A[0] = v.x; A[ASTR] = v.y; A[2 * ASTR] = v.z; A[3 * ASTR] = v.w;
        }
        for (int u = tid; u < 32 * bcnt; u += NTHR) {      // HHID/4 = 32
            const int k4 = u / bcnt;
            const int m  = u - k4 * bcnt;
            const float4 v = (t == 0)
                ? reinterpret_cast<const float4*>(h0l + (b0 + m) * HHID)[k4]
                : reinterpret_cast<const float4*>(g_h[q][l][b0 + m])[k4];
            float* A = sm + ASH_OFF + (Kin + k4 * 4) * ASTR + m;
            A[0] = v.x; A[ASTR] = v.y; A[2 * ASTR] = v.z; A[3 * ASTR] = v.w;
        }
    }
    __syncthreads();

    // ---- GEMM, split-K x2: thread (tx, ty, kz):
    //      rows {2ty, 2ty+1} x cols {6tx..6tx+5} over k-half kz -------------
    const int tx = tid & 15;
    const int ty = (tid >> 4) & 15;
    const int kz = tid >> 8;
    const int r0 = 2 * ty;

    float2 acc00 = make_float2(0.f, 0.f), acc01 = acc00, acc02 = acc00;
    float2 acc10 = acc00, acc11 = acc00, acc12 = acc00;

    const int Kh = K >> 1;                 // 96 or 128
    const int k0 = kz * Kh;
    const float4* W4 = reinterpret_cast<const float4*>(sm + WSH_OFF) + ty;
    const float*  Ap = sm + ASH_OFF + tx * 6;

    #pragma unroll 4
    for (int kk = k0; kk < k0 + Kh; ++kk) {
        const float4 w = W4[kk * 16];
        const float2 w01 = make_float2(w.x, w.y);
        const float2 w23 = make_float2(w.z, w.w);
        const float* A = Ap + kk * ASTR;
        const float2 a0 = *reinterpret_cast<const float2*>(A);
        const float2 a1 = *reinterpret_cast<const float2*>(A + 2);
        const float2 a2 = *reinterpret_cast<const float2*>(A + 4);
        acc00 = ffma2(a0, w01, acc00);
        acc10 = ffma2(a0, w23, acc10);
        acc01 = ffma2(a1, w01, acc01);
        acc11 = ffma2(a1, w23, acc11);
        acc02 = ffma2(a2, w01, acc02);
        acc12 = ffma2(a2, w23, acc12);
    }

    {
        float* Gp0 = sm + GSH_OFF + (kz * 32 + r0) * GSTR + tx * 6;
        float* Gp1 = Gp0 + GSTR;
        *reinterpret_cast<float2*>(Gp0    ) = acc00;
        *reinterpret_cast<float2*>(Gp0 + 2) = acc01;
        *reinterpret_cast<float2*>(Gp0 + 4) = acc02;
        *reinterpret_cast<float2*>(Gp1    ) = acc10;
        *reinterpret_cast<float2*>(Gp1 + 2) = acc11;
        *reinterpret_cast<float2*>(Gp1 + 4) = acc12;
    }
    __syncthreads();

    // ---- pointwise LSTM (sums both k-halves + bias); publish h, c ---------
    const int p = jstep & 1;
    const float* G0 = sm + GSH_OFF;
    const float* G1 = sm + GSH_OFF + 32 * GSTR;
    for (int i = tid; i < 8 * bcnt; i += NTHR) {
        const int jj = i & 7, m = i >> 3;
        const int jl = jc * 8 + jj;
        const float gi = G0[(     jj) * GSTR + m] + G1[(     jj) * GSTR + m]
                       + bl[      jl];
        const float gf = G0[( 8 + jj) * GSTR + m] + G1[( 8 + jj) * GSTR + m]
                       + bl[128 + jl];
        const float go = G0[(16 + jj) * GSTR + m] + G1[(16 + jj) * GSTR + m]
                       + bl[256 + jl];
        const float gg = G0[(24 + jj) * GSTR + m] + G1[(24 + jj) * GSTR + m]
                       + bl[384 + jl];
        const int b = b0 + m;
        float c = (t == 0) ? c0l[b * HHID + jl] : g_c[l][b][jl];
        const float si = __fdividef(1.f, 1.f + __expf(-gi));
        const float sf = __fdividef(1.f, 1.f + __expf(-gf));
        const float so = __fdividef(1.f, 1.f + __expf(-go));
        c = sf * c + si * tanhf(gg);
        const float h = so * tanhf(c);
        g_c[l][b][jl] = c;
        g_h[p][l][b][jl] = h;
        if (l == 2 && t == T - 1)
            out[b * HHID + jl] = h;
    }
}

// ---------------------------------------------------------------------------
extern "C" void kernel_launch(void* const* d_in, const int* in_sizes, int n_in,
                              void* d_out, int out_size)
{
    const float* x   = (const float*)d_in[0];
    const float* W1  = (const float*)d_in[1];
    const float* b1  = (const float*)d_in[2];
    const float* W2  = (const float*)d_in[3];
    const float* b2  = (const float*)d_in[4];
    const float* W3  = (const float*)d_in[5];
    const float* b3  = (const float*)d_in[6];
    const float* h01 = (const float*)d_in[7];
    const float* c01 = (const float*)d_in[8];
    const float* h02 = (const float*)d_in[9];
    const float* c02 = (const float*)d_in[10];
    const float* h03 = (const float*)d_in[11];
    const float* c03 = (const float*)d_in[12];
    float* out = (float*)d_out;
    (void)n_in; (void)out_size;

    const int Tx = in_sizes[0] / (BBATCH * CIN);   // = 512 = seq_len
    const int T  = Tx;

    cudaFuncSetAttribute(step_kernel,
                         cudaFuncAttributeMaxDynamicSharedMemorySize,
                         SMEM_BYTES);

    prep_kernel<<<192, 256>>>(W1, W2, W3);
    for (int j = 0; j < T + 2; ++j)
        step_kernel<<<GRID_MAIN, NTHR, SMEM_BYTES>>>(
            x, b1, b2, b3, h01, c01, h02, c02, h03, c03,
            out, j, T, Tx);
}

// round 8
// speedup vs baseline: 1.0541x; 1.0040x over previous
#include <cuda_runtime.h>
#include <cstdint>
#include <cstddef>

// ============================================================================
// ConvLSTM encoder == 3-layer stacked LSTM (K=3 conv over a length-1 spatial
// dim, pad 1 -> only center tap W[:,:,1] contributes).
//
// Multi-launch skewed pipeline: launch j computes layer0@t=j, layer1@t=j-1,
// layer2@t=j-2; dependencies are kernel-boundary ordering.
// This round: 1024 threads (32 warps/SM), split-K x4, Gsh overlaid on Ash
// (SMEM 166 KB, extra barrier separates the lifetimes).
// ============================================================================

#define BBATCH 256
#define HHID   128
#define CIN    64
#define JC_N   16                      // hidden chunks per layer (8 hidden each)
#define BG_N   3                       // batch groups (85/85/86)
#define CTA_PER_LAYER (JC_N*BG_N)      // 48
#define GRID_MAIN (3*CTA_PER_LAYER)    // 144
#define NTHR 1024
#define KSPLIT 4

// SMEM (floats): Ash [256][98] | Wsh splat pairs [256][64]
// Gsh [4][32][98] overlays Ash (live only after GEMM; extra barrier).
#define ASTR    98
#define ASH_OFF 0
#define GSH_OFF 0
#define GSTR    98
#define WSH_OFF (256*ASTR)                      // 25088
#define SMEM_FLOATS (WSH_OFF + 256*64)          // 41472
#define SMEM_BYTES  (SMEM_FLOATS*4)             // 165888 B

// Weight pack: per (layer, jc-chunk): [k][64] = splat pairs of the 32 gate
// rows owned by that chunk. 3 MB, L2-resident.
__device__ float g_wsplat[3*16*256*64];
__device__ float g_h[2][3][BBATCH][HHID];        // parity double buffer
__device__ float g_c[3][BBATCH][HHID];

// ---------------------------------------------------------------------------
__device__ __forceinline__ float2 ffma2(float2 a, float2 b, float2 c) {
    unsigned long long ua = *reinterpret_cast<unsigned long long*>(&a);
    unsigned long long ub = *reinterpret_cast<unsigned long long*>(&b);
    unsigned long long uc = *reinterpret_cast<unsigned long long*>(&c);
    unsigned long long ud;
    asm("fma.rn.f32x2 %0, %1, %2, %3;" : "=l"(ud) : "l"(ua), "l"(ub), "l"(uc));
    float2 d;
    *reinterpret_cast<unsigned long long*>(&d) = ud;
    return d;
}

// ---------------------------------------------------------------------------
// Build g_wsplat: for (l, jc, k, r<32): row o = (r>>3)*128 + jc*8 + (r&7);
// value W[o][k][1] written twice at [..][k][2r] and [2r+1].
__global__ void prep_kernel(const float* __restrict__ W1,
                            const float* __restrict__ W2,
                            const float* __restrict__ W3)
{
    const int total = 3 * 16 * 256 * 32;
    for (int u = blockIdx.x * blockDim.x + threadIdx.x;
         u < total; u += gridDim.x * blockDim.x) {
        const int r  = u & 31;
        const int k  = (u >> 5) & 255;
        const int jc = (u >> 13) & 15;
        const int l  = u >> 17;
        const int K  = (l == 0) ? (CIN + HHID) : (2 * HHID);
        if (k < K) {
            const float* W = (l == 0) ? W1 : ((l == 1) ? W2 : W3);
            const int o = (r >> 3) * 128 + jc * 8 + (r & 7);
            const float v = W[((size_t)o * K + k) * 3 + 1];
            float* dst = g_wsplat + (((l * 16 + jc) * 256 + k) << 6) + 2 * r;
            dst[0] = v;
            dst[1] = v;
        }
    }
}

// ---------------------------------------------------------------------------
__global__ void __launch_bounds__(NTHR)
step_kernel(const float* __restrict__ x,
            const float* __restrict__ b1, const float* __restrict__ b2,
            const float* __restrict__ b3,
            const float* __restrict__ h01, const float* __restrict__ c01,
            const float* __restrict__ h02, const float* __restrict__ c02,
            const float* __restrict__ h03, const float* __restrict__ c03,
            float* __restrict__ out, int jstep, int T, int Tx)
{
    const int l = blockIdx.x / CTA_PER_LAYER;
    const int t = jstep - l;
    if (t < 0 || t >= T) return;

    extern __shared__ float sm[];
    const int tid = threadIdx.x;
    const int r   = blockIdx.x % CTA_PER_LAYER;
    const int jc  = r % JC_N;
    const int bg  = r / JC_N;
    const int b0   = (bg * BBATCH) / BG_N;
    const int bcnt = ((bg + 1) * BBATCH) / BG_N - b0;    // 85/85/86
    const int Kin  = (l == 0) ? CIN : HHID;
    const int K    = Kin + HHID;                          // 192 or 256
    const int q    = (jstep - 1) & 1;                     // read parity

    const float* bl  = (l == 0) ? b1  : ((l == 1) ? b2  : b3);
    const float* h0l = (l == 0) ? h01 : ((l == 1) ? h02 : h03);
    const float* c0l = (l == 0) ? c01 : ((l == 1) ? c02 : c03);

    // ---- stage weights: contiguous float4 copy of the pre-splatted chunk --
    {
        const float4* src = reinterpret_cast<const float4*>(
            g_wsplat + ((size_t)(l * 16 + jc) << 14));    // *256*64
        float4* dst = reinterpret_cast<float4*>(sm + WSH_OFF);
        const int n4 = K * 16;                            // K*64/4
        for (int u = tid; u < n4; u += NTHR)
            dst[u] = src[u];
    }

    // ---- stage activations: Ash[k][m], m-fast (conflict-free STS) ---------
    {
        const int kz4 = Kin >> 2;
        for (int u = tid; u < kz4 * bcnt; u += NTHR) {
            const int k4 = u / bcnt;
            const int m  = u - k4 * bcnt;
            float4 v;
            if (l == 0)
                v = reinterpret_cast<const float4*>(
                        x + ((size_t)(b0 + m) * Tx + t) * CIN)[k4];
            else
                v = reinterpret_cast<const float4*>(g_h[q][l - 1][b0 + m])[k4];
            float* A = sm + ASH_OFF + (k4 * 4) * ASTR + m;
            A[0] = v.x; A[ASTR] = v.y; A[2 * ASTR] = v.z; A[3 * ASTR] = v.w;
        }
        for (int u = tid; u < 32 * bcnt; u += NTHR) {      // HHID/4 = 32
            const int k4 = u / bcnt;
            const int m  = u - k4 * bcnt;
            const float4 v = (t == 0)
                ? reinterpret_cast<const float4*>(h0l + (b0 + m) * HHID)[k4]
                : reinterpret_cast<const float4*>(g_h[q][l][b0 + m])[k4];
            float* A = sm + ASH_OFF + (Kin + k4 * 4) * ASTR + m;
            A[0] = v.x; A[ASTR] = v.y; A[2 * ASTR] = v.z; A[3 * ASTR] = v.w;
        }
    }
    __syncthreads();

    // ---- GEMM, split-K x4: thread (tx, ty, kz):
    //      rows {2ty, 2ty+1} x cols {6tx..6tx+5} over k-quarter kz ----------
    const int tx = tid & 15;
    const int ty = (tid >> 4) & 15;
    const int kz = tid >> 8;               // 0..3
    const int r0 = 2 * ty;

    float2 acc00 = make_float2(0.f, 0.f), acc01 = acc00, acc02 = acc00;
    float2 acc10 = acc00, acc11 = acc00, acc12 = acc00;

    const int Kh = K >> 2;                 // 48 or 64
    const int k0 = kz * Kh;
    const float4* W4 = reinterpret_cast<const float4*>(sm + WSH_OFF) + ty;
    const float*  Ap = sm + ASH_OFF + tx * 6;

    #pragma unroll 8
    for (int kk = k0; kk < k0 + Kh; ++kk) {
        const float4 w = W4[kk * 16];
        const float2 w01 = make_float2(w.x, w.y);
        const float2 w23 = make_float2(w.z, w.w);
        const float* A = Ap + kk * ASTR;
        const float2 a0 = *reinterpret_cast<const float2*>(A);
        const float2 a1 = *reinterpret_cast<const float2*>(A + 2);
        const float2 a2 = *reinterpret_cast<const float2*>(A + 4);
        acc00 = ffma2(a0, w01, acc00);
        acc10 = ffma2(a0, w23, acc10);
        acc01 = ffma2(a1, w01, acc01);
        acc11 = ffma2(a1, w23, acc11);
        acc02 = ffma2(a2, w01, acc02);
        acc12 = ffma2(a2, w23, acc12);
    }

    // Gsh overlays Ash: wait until ALL threads are done reading Ash.
    __syncthreads();

    {
        float* Gp0 = sm + GSH_OFF + (kz * 32 + r0) * GSTR + tx * 6;
        float* Gp1 = Gp0 + GSTR;
        *reinterpret_cast<float2*>(Gp0    ) = acc00;
        *reinterpret_cast<float2*>(Gp0 + 2) = acc01;
        *reinterpret_cast<float2*>(Gp0 + 4) = acc02;
        *reinterpret_cast<float2*>(Gp1    ) = acc10;
        *reinterpret_cast<float2*>(Gp1 + 2) = acc11;
        *reinterpret_cast<float2*>(Gp1 + 4) = acc12;
    }
    __syncthreads();

    // ---- pointwise LSTM (sums 4 k-partials + bias); publish h, c ----------
    const int p = jstep & 1;
    const float* G0 = sm + GSH_OFF;
    const float* G1 = G0 + 32 * GSTR;
    const float* G2 = G1 + 32 * GSTR;
    const float* G3 = G2 + 32 * GSTR;
    for (int i = tid; i < 8 * bcnt; i += NTHR) {
        const int jj = i & 7, m = i >> 3;
        const int jl = jc * 8 + jj;
        const int o0 = (     jj) * GSTR + m;
        const int o1 = ( 8 + jj) * GSTR + m;
        const int o2 = (16 + jj) * GSTR + m;
        const int o3 = (24 + jj) * GSTR + m;
        const float gi = G0[o0] + G1[o0] + G2[o0] + G3[o0] + bl[      jl];
        const float gf = G0[o1] + G1[o1] + G2[o1] + G3[o1] + bl[128 + jl];
        const float go = G0[o2] + G1[o2] + G2[o2] + G3[o2] + bl[256 + jl];
        const float gg = G0[o3] + G1[o3] + G2[o3] + G3[o3] + bl[384 + jl];
        const int b = b0 + m;
        float c = (t == 0) ? c0l[b * HHID + jl] : g_c[l][b][jl];
        const float si = __fdividef(1.f, 1.f + __expf(-gi));
        const float sf = __fdividef(1.f, 1.f + __expf(-gf));
        const float so = __fdividef(1.f, 1.f + __expf(-go));
        c = sf * c + si * tanhf(gg);
        const float h = so * tanhf(c);
        g_c[l][b][jl] = c;
        g_h[p][l][b][jl] = h;
        if (l == 2 && t == T - 1)
            out[b * HHID + jl] = h;
    }
}

// ---------------------------------------------------------------------------
extern "C" void kernel_launch(void* const* d_in, const int* in_sizes, int n_in,
                              void* d_out, int out_size)
{
    const float* x   = (const float*)d_in[0];
    const float* W1  = (const float*)d_in[1];
    const float* b1  = (const float*)d_in[2];
    const float* W2  = (const float*)d_in[3];
    const float* b2  = (const float*)d_in[4];
    const float* W3  = (const float*)d_in[5];
    const float* b3  = (const float*)d_in[6];
    const float* h01 = (const float*)d_in[7];
    const float* c01 = (const float*)d_in[8];
    const float* h02 = (const float*)d_in[9];
    const float* c02 = (const float*)d_in[10];
    const float* h03 = (const float*)d_in[11];
    const float* c03 = (const float*)d_in[12];
    float* out = (float*)d_out;
    (void)n_in; (void)out_size;

    const int Tx = in_sizes[0] / (BBATCH * CIN);   // = 512 = seq_len
    const int T  = Tx;

    cudaFuncSetAttribute(step_kernel,
                         cudaFuncAttributeMaxDynamicSharedMemorySize,
                         SMEM_BYTES);

    prep_kernel<<<192, 256>>>(W1, W2, W3);
    for (int j = 0; j < T + 2; ++j)
        step_kernel<<<GRID_MAIN, NTHR, SMEM_BYTES>>>(
            x, b1, b2, b3, h01, c01, h02, c02, h03, c03,
            out, j, T, Tx);
}

// round 9
// speedup vs baseline: 1.1088x; 1.0519x over previous
#include <cuda_runtime.h>
#include <cstdint>
#include <cstddef>

// ============================================================================
// ConvLSTM encoder == 3-layer stacked LSTM (K=3 conv over a length-1 spatial
// dim, pad 1 -> only center tap W[:,:,1] contributes).
//
// PERSISTENT kernel: 144 CTAs (3 layers x 3 batch-groups x 16 hidden-chunks),
// 169KB smem -> 1 CTA/SM, grid 144 <= 148 SMs -> all co-resident (one wave).
// Weights + cell state stay in SMEM for all T steps. Cross-CTA handoff of h
// via transposed global ring [l][slot][j][b] + per-(layer,bg) 16-flag groups.
// Spin-waits are watchdog-capped with a global abort latch (no hangs).
// ============================================================================

#define BBATCH 256
#define HHID   128
#define CIN    64
#define JC_N   16
#define BG_N   3
#define CTA_PER_LAYER (JC_N*BG_N)      // 48
#define GRID_MAIN (3*CTA_PER_LAYER)    // 144
#define NTHR 1024
#define RING 8

// SMEM (floats): Ash [256][100] (Gsh [4][32][100] overlays it) | Wsh [256][64]
//                Csh [88*8] | Bsh [32]
#define ASTR    100
#define GSTR    100
#define ASH_OFF 0
#define GSH_OFF 0
#define WSH_OFF (256*ASTR)                  // 25600
#define CSH_OFF (WSH_OFF + 256*64)          // 41984
#define BSH_OFF (CSH_OFF + 88*8)            // 42688
#define SMEM_FLOATS (BSH_OFF + 32)          // 42720
#define SMEM_BYTES  (SMEM_FLOATS*4)         // 170880 B (< 227KB opt-in)

__device__ float g_wsplat[3*16*256*64];          // 3 MB packed splat pairs
__device__ float g_xT[512*64*256];               // 32 MB: x as [t][k][b]
__device__ float g_hring[3][RING][HHID][BBATCH]; // transposed h ring, 3 MB
__device__ int4  g_flags4[9][4];                 // [l*3+bg][16 flags]
__device__ volatile int g_abort;

// ---------------------------------------------------------------------------
__device__ __forceinline__ float2 ffma2(float2 a, float2 b, float2 c) {
    unsigned long long ua = *reinterpret_cast<unsigned long long*>(&a);
    unsigned long long ub = *reinterpret_cast<unsigned long long*>(&b);
    unsigned long long uc = *reinterpret_cast<unsigned long long*>(&c);
    unsigned long long ud;
    asm("fma.rn.f32x2 %0, %1, %2, %3;" : "=l"(ud) : "l"(ua), "l"(ub), "l"(uc));
    float2 d;
    *reinterpret_cast<unsigned long long*>(&d) = ud;
    return d;
}

#define LD_REL4(v, p)                                                        \
    asm volatile("ld.relaxed.gpu.global.v4.f32 {%0,%1,%2,%3}, [%4];"         \
                 : "=f"((v).x), "=f"((v).y), "=f"((v).z), "=f"((v).w)        \
                 : "l"(p))

// Poll 16 flags until all >= val. Watchdog: cap spins, set abort, fall thru.
__device__ __forceinline__ void wait16(const int4* p, int val) {
    int spins = 0;
    while (true) {
        bool ok = true;
        #pragma unroll
        for (int i = 0; i < 4; ++i) {
            int4 v;
            asm volatile("ld.relaxed.gpu.global.v4.b32 {%0,%1,%2,%3}, [%4];"
                         : "=r"(v.x), "=r"(v.y), "=r"(v.z), "=r"(v.w)
                         : "l"(p + i));
            ok &= (v.x >= val) & (v.y >= val) & (v.z >= val) & (v.w >= val);
        }
        if (ok) return;
        if (((++spins) & 63) == 0) {
            if (g_abort) return;
            if (spins > (1 << 22)) { g_abort = 1; return; }
        }
        __nanosleep(32);
    }
}

// ---------------------------------------------------------------------------
__global__ void reset_kernel() {
    int i = threadIdx.x;
    if (i < 9 * 16) ((int*)g_flags4)[i] = 0;
    if (i == 0) g_abort = 0;
}

// Pack center-tap weights as splat pairs per (l, jc): [k][64].
__global__ void pack_kernel(const float* __restrict__ W1,
                            const float* __restrict__ W2,
                            const float* __restrict__ W3)
{
    const int total = 3 * 16 * 256 * 32;
    for (int u = blockIdx.x * blockDim.x + threadIdx.x;
         u < total; u += gridDim.x * blockDim.x) {
        const int r  = u & 31;
        const int k  = (u >> 5) & 255;
        const int jc = (u >> 13) & 15;
        const int l  = u >> 17;
        const int K  = (l == 0) ? (CIN + HHID) : (2 * HHID);
        if (k < K) {
            const float* W = (l == 0) ? W1 : ((l == 1) ? W2 : W3);
            const int o = (r >> 3) * 128 + jc * 8 + (r & 7);
            const float v = W[((size_t)o * K + k) * 3 + 1];
            float* dst = g_wsplat + (((l * 16 + jc) * 256 + k) << 6) + 2 * r;
            dst[0] = v;
            dst[1] = v;
        }
    }
}

// Transpose x[b][t][k] -> g_xT[t][k][b], tiled through SMEM.
__global__ void xpose_kernel(const float* __restrict__ x, int T) {
    __shared__ float tile[64][65];
    const int t  = blockIdx.x;
    const int b0 = blockIdx.y * 64;
    const int tid = threadIdx.x;
    for (int u = tid; u < 64 * 64; u += 256) {
        const int bb = u >> 6, k = u & 63;
        tile[k][bb] = x[((size_t)(b0 + bb) * T + t) * CIN + k];
    }
    __syncthreads();
    for (int u = tid; u < 64 * 64; u += 256) {
        const int k = u >> 6, bb = u & 63;
        g_xT[((size_t)t * CIN + k) * BBATCH + b0 + bb] = tile[k][bb];
    }
}

// Prefill ring slot RING-1 with transposed h0 (read by own-layer at t=0).
__global__ void ringinit_kernel(const float* __restrict__ h01,
                                const float* __restrict__ h02,
                                const float* __restrict__ h03)
{
    const int u = blockIdx.x * blockDim.x + threadIdx.x;
    if (u < 3 * HHID * BBATCH) {
        const int l = u / (HHID * BBATCH);
        const int rem = u - l * HHID * BBATCH;
        const int j = rem >> 8;        // /256
        const int b = rem & 255;
        const float* h0 = (l == 0) ? h01 : ((l == 1) ? h02 : h03);
        g_hring[l][RING - 1][j][b] = h0[b * HHID + j];
    }
}

// ---------------------------------------------------------------------------
__global__ void __launch_bounds__(NTHR, 1)
lstm_persistent(const float* __restrict__ b1, const float* __restrict__ b2,
                const float* __restrict__ b3,
                const float* __restrict__ c01, const float* __restrict__ c02,
                const float* __restrict__ c03,
                float* __restrict__ out, int T)
{
    extern __shared__ float sm[];
    const int tid = threadIdx.x;
    const int l   = blockIdx.x / CTA_PER_LAYER;
    const int rr  = blockIdx.x % CTA_PER_LAYER;
    const int jc  = rr & 15;
    const int bg  = rr >> 4;
    const int b0   = bg * 88;
    const int bcnt = (bg == 2) ? 80 : 88;
    const int Kin  = (l == 0) ? CIN : HHID;
    const int K    = Kin + HHID;

    const float* bl  = (l == 0) ? b1  : ((l == 1) ? b2  : b3);
    const float* c0l = (l == 0) ? c01 : ((l == 1) ? c02 : c03);

    // ---- one-time: weights, bias, cell state into SMEM --------------------
    {
        const float4* src = reinterpret_cast<const float4*>(
            g_wsplat + ((size_t)(l * 16 + jc) << 14));
        float4* dst = reinterpret_cast<float4*>(sm + WSH_OFF);
        for (int u = tid; u < K * 16; u += NTHR)
            dst[u] = src[u];
    }
    if (tid < 32)
        sm[BSH_OFF + tid] = bl[(tid >> 3) * 128 + jc * 8 + (tid & 7)];
    for (int i = tid; i < bcnt * 8; i += NTHR) {
        const int m = i >> 3, jj = i & 7;
        sm[CSH_OFF + i] = c0l[(b0 + m) * HHID + jc * 8 + jj];
    }
    __syncthreads();

    const int4* flag_own  = g_flags4[l * 3 + bg];
    const int4* flag_low  = (l > 0) ? g_flags4[(l - 1) * 3 + bg] : nullptr;
    const int4* flag_down = (l < 2) ? g_flags4[(l + 1) * 3 + bg] : nullptr;
    int* myflag = &((int*)g_flags4[l * 3 + bg])[jc];

    const int tx = tid & 15;
    const int ty = (tid >> 4) & 15;
    const int kz = tid >> 8;               // 0..3
    const int r0 = 2 * ty;
    const int Kh = K >> 2;
    const int k0 = kz * Kh;
    const float4* W4 = reinterpret_cast<const float4*>(sm + WSH_OFF) + ty;
    const float*  Ap = sm + ASH_OFF + tx * 6;

    for (int t = 0; t < T; ++t) {
        // ---- dependency waits (thread 0), then barrier --------------------
        if (tid == 0) {
            if (t > 0)            wait16(flag_own, t);
            if (l > 0)            wait16(flag_low, t + 1);
            if (l < 2 && t >= RING) wait16(flag_down, t - RING + 1);
            asm volatile("fence.acq_rel.gpu;" ::: "memory");
        }
        __syncthreads();

        const int slot  = t & (RING - 1);
        const int pslot = (t - 1) & (RING - 1);

        // ---- stage activations: Ash[k][m], cols padded/zeroed to 96 -------
        {
            const int nb4z = 24;                       // 96 cols / 4
            for (int u = tid; u < K * nb4z; u += NTHR) {
                const int k  = u / nb4z;
                const int m4 = u - k * nb4z;
                float4 v;
                if (4 * m4 >= bcnt) {
                    v = make_float4(0.f, 0.f, 0.f, 0.f);
                } else if (k < Kin) {
                    if (l == 0)
                        v = *reinterpret_cast<const float4*>(
                            g_xT + ((size_t)t * CIN + k) * BBATCH + b0 + 4 * m4);
                    else
                        LD_REL4(v, &g_hring[l - 1][slot][k][b0 + 4 * m4]);
                } else {
                    LD_REL4(v, &g_hring[l][pslot][k - Kin][b0 + 4 * m4]);
                }
                *reinterpret_cast<float4*>(sm + ASH_OFF + k * ASTR + 4 * m4) = v;
            }
        }
        __syncthreads();

        // ---- GEMM, split-K x4: rows {r0,r0+1} x cols {6tx..6tx+5} ---------
        float2 acc00 = make_float2(0.f, 0.f), acc01 = acc00, acc02 = acc00;
        float2 acc10 = acc00, acc11 = acc00, acc12 = acc00;
        #pragma unroll 8
        for (int kk = k0; kk < k0 + Kh; ++kk) {
            const float4 w = W4[kk * 16];
            const float2 w01 = make_float2(w.x, w.y);
            const float2 w23 = make_float2(w.z, w.w);
            const float* A = Ap + kk * ASTR;
            const float2 a0 = *reinterpret_cast<const float2*>(A);
            const float2 a1 = *reinterpret_cast<const float2*>(A + 2);
            const float2 a2 = *reinterpret_cast<const float2*>(A + 4);
            acc00 = ffma2(a0, w01, acc00);
            acc10 = ffma2(a0, w23, acc10);
            acc01 = ffma2(a1, w01, acc01);
            acc11 = ffma2(a1, w23, acc11);
            acc02 = ffma2(a2, w01, acc02);
            acc12 = ffma2(a2, w23, acc12);
        }

        __syncthreads();   // Gsh overlays Ash: all reads of Ash must be done

        {
            float* Gp0 = sm + GSH_OFF + (kz * 32 + r0) * GSTR + tx * 6;
            float* Gp1 = Gp0 + GSTR;
            *reinterpret_cast<float2*>(Gp0    ) = acc00;
            *reinterpret_cast<float2*>(Gp0 + 2) = acc01;
            *reinterpret_cast<float2*>(Gp0 + 4) = acc02;
            *reinterpret_cast<float2*>(Gp1    ) = acc10;
            *reinterpret_cast<float2*>(Gp1 + 2) = acc11;
            *reinterpret_cast<float2*>(Gp1 + 4) = acc12;
        }
        __syncthreads();

        // ---- pointwise LSTM (4 partials + bias); h -> transposed ring -----
        const float* G0 = sm + GSH_OFF;
        const float* G1 = G0 + 32 * GSTR;
        const float* G2 = G1 + 32 * GSTR;
        const float* G3 = G2 + 32 * GSTR;
        for (int i = tid; i < 8 * bcnt; i += NTHR) {
            const int jj = i & 7, m = i >> 3;
            const int o0 = (     jj) * GSTR + m;
            const int o1 = ( 8 + jj) * GSTR + m;
            const int o2 = (16 + jj) * GSTR + m;
            const int o3 = (24 + jj) * GSTR + m;
            const float gi = G0[o0] + G1[o0] + G2[o0] + G3[o0] + sm[BSH_OFF +      jj];
            const float gf = G0[o1] + G1[o1] + G2[o1] + G3[o1] + sm[BSH_OFF +  8 + jj];
            const float go = G0[o2] + G1[o2] + G2[o2] + G3[o2] + sm[BSH_OFF + 16 + jj];
            const float gg = G0[o3] + G1[o3] + G2[o3] + G3[o3] + sm[BSH_OFF + 24 + jj];
            float c = sm[CSH_OFF + i];
            const float si = __fdividef(1.f, 1.f + __expf(-gi));
            const float sf = __fdividef(1.f, 1.f + __expf(-gf));
            const float so = __fdividef(1.f, 1.f + __expf(-go));
            c = sf * c + si * tanhf(gg);
            const float h = so * tanhf(c);
            sm[CSH_OFF + i] = c;
            g_hring[l][slot][jc * 8 + jj][b0 + m] = h;
            if (l == 2 && t == T - 1)
                out[(b0 + m) * HHID + jc * 8 + jj] = h;
        }

        asm volatile("fence.acq_rel.gpu;" ::: "memory");
        __syncthreads();
        if (tid == 0)
            asm volatile("st.relaxed.gpu.global.s32 [%0], %1;"
                         :: "l"(myflag), "r"(t + 1) : "memory");
    }
}

// ---------------------------------------------------------------------------
extern "C" void kernel_launch(void* const* d_in, const int* in_sizes, int n_in,
                              void* d_out, int out_size)
{
    const float* x   = (const float*)d_in[0];
    const float* W1  = (const float*)d_in[1];
    const float* b1  = (const float*)d_in[2];
    const float* W2  = (const float*)d_in[3];
    const float* b2  = (const float*)d_in[4];
    const float* W3  = (const float*)d_in[5];
    const float* b3  = (const float*)d_in[6];
    const float* h01 = (const float*)d_in[7];
    const float* c01 = (const float*)d_in[8];
    const float* h02 = (const float*)d_in[9];
    const float* c02 = (const float*)d_in[10];
    const float* h03 = (const float*)d_in[11];
    const float* c03 = (const float*)d_in[12];
    float* out = (float*)d_out;
    (void)n_in; (void)out_size;

    const int Tx = in_sizes[0] / (BBATCH * CIN);   // = 512 = seq_len

    cudaFuncSetAttribute(lstm_persistent,
                         cudaFuncAttributeMaxDynamicSharedMemorySize,
                         SMEM_BYTES);

    reset_kernel<<<1, 256>>>();
    pack_kernel<<<192, 256>>>(W1, W2, W3);
    xpose_kernel<<<dim3(Tx, 4), 256>>>(x, Tx);
    ringinit_kernel<<<(3 * HHID * BBATCH + 255) / 256, 256>>>(h01, h02, h03);
    lstm_persistent<<<GRID_MAIN, NTHR, SMEM_BYTES>>>(
        b1, b2, b3, c01, c02, c03, out, Tx);
}